// round 17
// baseline (speedup 1.0000x reference)
#include <cuda_runtime.h>
#include <math.h>

// ---------------------------------------------------------------------------
// SubgraphAttention — see prior rounds. All math fp32; GEMMs use packed
// fma.rn.f32x2 (bit-exact IEEE fp32).
// R17: widen score_kernel's per-thread tile (2Mx2N -> 2Mx4N + col64, BK 16->32,
// 128 thr). R16 evidence: score=26.1us, fma 13.2%, L1 40.4% — same
// LDS-per-MAC disease R8 fixed in gemm_T. Per-element arithmetic unchanged.
// ---------------------------------------------------------------------------

#define BB 32
#define NN 65
#define SS 64
#define DD 512
#define MROWS (BB * NN)   // 2080

static const size_t OUT_ELEMS  = (size_t)BB * SS * NN * DD;    // 68,157,440
static const size_t LEADER_OFF = OUT_ELEMS;
static const size_t MEMBER_OFF = OUT_ELEMS + (size_t)BB * SS;

// gemm_T dynamic smem layout: As[2][32][130] then Bs[2][32][64]
#define TT_APAD 130
static const int GT_SMEM = (2 * 32 * TT_APAD + 2 * 32 * 64) * 4;  // 49,664 B

// ----------------------------- device scratch ------------------------------
__device__ float g_Cp[4][DD * DD];        // C split-K partials
__device__ float g_C[DD * DD];            // reduced C
__device__ float g_T[MROWS * DD];
__device__ float g_v1[DD];
__device__ float g_v2[DD];
__device__ float g_s0;
__device__ float g_u1[MROWS];
__device__ float g_u2[MROWS];
__device__ unsigned long long g_rawmask[BB * SS];
__device__ unsigned long long g_mmask[BB * SS];

// ----------------------------- f32x2 helpers -------------------------------
__device__ __forceinline__ void fma2(unsigned long long& d, unsigned long long a,
                                     unsigned long long b) {
    asm("fma.rn.f32x2 %0, %1, %2, %0;" : "+l"(d) : "l"(a), "l"(b));
}
__device__ __forceinline__ unsigned long long bcast2(float x) {
    unsigned long long r;
    asm("mov.b64 %0, {%1, %1};" : "=l"(r) : "f"(x));
    return r;
}
__device__ __forceinline__ float2 unpk2(unsigned long long v) {
    float2 r;
    asm("mov.b64 {%0, %1}, %2;" : "=f"(r.x), "=f"(r.y) : "l"(v));
    return r;
}

// ----------------------------------------------------------------------------
// stage1: blocks 0..31 = prep (v1/v2/s0); blocks 32..287 = gemm_C split-K=4.
// ----------------------------------------------------------------------------
__global__ __launch_bounds__(128) void stage1_kernel(const float* __restrict__ Wq,
                                                     const float* __restrict__ bq,
                                                     const float* __restrict__ Wk,
                                                     const float* __restrict__ bk) {
    const int tid = threadIdx.x;
    const int bx = blockIdx.x;

    if (bx < 32) {
        __shared__ float sb[512];
        __shared__ float part[4][32];
        __shared__ float red[128];
        const int mat = bx >> 4;
        const int c0 = (bx & 15) * 32;
        const float* W = mat ? Wk : Wq;
        const float* bv = mat ? bq : bk;

        for (int i = tid; i < 512; i += 128) sb[i] = bv[i];
        __syncthreads();

        const int c = c0 + (tid & 31);
        const int q = tid >> 5;
        const int n0 = q * 128;
        float acc = 0.f;
#pragma unroll 8
        for (int n = 0; n < 128; n++) {
            acc += W[(n0 + n) * 512 + c] * sb[n0 + n];
        }
        part[q][tid & 31] = acc;
        __syncthreads();
        if (tid < 32) {
            float v = ((part[0][tid] + part[1][tid]) + part[2][tid]) + part[3][tid];
            (mat ? g_v2 : g_v1)[c0 + tid] = v;
        }
        if (bx == 0) {
            red[tid] = bq[tid] * bk[tid] + bq[tid + 128] * bk[tid + 128] +
                       bq[tid + 256] * bk[tid + 256] + bq[tid + 384] * bk[tid + 384];
            __syncthreads();
            for (int s = 64; s > 0; s >>= 1) {
                if (tid < s) red[tid] += red[tid + s];
                __syncthreads();
            }
            if (tid == 0) g_s0 = red[0];
        }
        return;
    }

    // ---- gemm_C branch ----
    __shared__ __align__(16) float As[2][32][68];
    __shared__ __align__(16) float Bs[2][32][64];
    const int g = bx - 32;
    const int tm = tid & 15;
    const int tn = tid >> 4;
    const int bm0 = (g & 7) * 64;
    const int bn0 = ((g >> 3) & 7) * 64;
    const int kbase = (g >> 6) * 128;

    unsigned long long acc[16];
#pragma unroll
    for (int i = 0; i < 16; i++) acc[i] = 0ull;

    float4 ra[4], rb[4];
#pragma unroll
    for (int it = 0; it < 4; it++) {
        int idx = tid + it * 128;
        int r = idx >> 4, c4 = (idx & 15) * 4;
        ra[it] = *reinterpret_cast<const float4*>(&Wq[(kbase + r) * 512 + bm0 + c4]);
        rb[it] = *reinterpret_cast<const float4*>(&Wk[(kbase + r) * 512 + bn0 + c4]);
    }
#pragma unroll
    for (int it = 0; it < 4; it++) {
        int idx = tid + it * 128;
        int r = idx >> 4, c4 = (idx & 15) * 4;
        *reinterpret_cast<float4*>(&As[0][r][c4]) = ra[it];
        *reinterpret_cast<float4*>(&Bs[0][r][c4]) = rb[it];
    }
    __syncthreads();

    for (int kt = 0; kt < 4; kt++) {
        const int cur = kt & 1, nxt = cur ^ 1;
        if (kt < 3) {
            int k0 = kbase + (kt + 1) * 32;
#pragma unroll
            for (int it = 0; it < 4; it++) {
                int idx = tid + it * 128;
                int r = idx >> 4, c4 = (idx & 15) * 4;
                ra[it] = *reinterpret_cast<const float4*>(&Wq[(k0 + r) * 512 + bm0 + c4]);
                rb[it] = *reinterpret_cast<const float4*>(&Wk[(k0 + r) * 512 + bn0 + c4]);
            }
        }
#pragma unroll
        for (int k = 0; k < 32; k++) {
            unsigned long long a0 = *reinterpret_cast<const unsigned long long*>(&As[cur][k][2 * tm]);
            unsigned long long a1 = *reinterpret_cast<const unsigned long long*>(&As[cur][k][2 * tm + 32]);
            float4 b0 = *reinterpret_cast<const float4*>(&Bs[cur][k][8 * tn]);
            float4 b1 = *reinterpret_cast<const float4*>(&Bs[cur][k][8 * tn + 4]);
            unsigned long long bb[8] = {bcast2(b0.x), bcast2(b0.y), bcast2(b0.z), bcast2(b0.w),
                                        bcast2(b1.x), bcast2(b1.y), bcast2(b1.z), bcast2(b1.w)};
#pragma unroll
            for (int n = 0; n < 8; n++) {
                fma2(acc[n], a0, bb[n]);
                fma2(acc[8 + n], a1, bb[n]);
            }
        }
        if (kt < 3) {
#pragma unroll
            for (int it = 0; it < 4; it++) {
                int idx = tid + it * 128;
                int r = idx >> 4, c4 = (idx & 15) * 4;
                *reinterpret_cast<float4*>(&As[nxt][r][c4]) = ra[it];
                *reinterpret_cast<float4*>(&Bs[nxt][r][c4]) = rb[it];
            }
            __syncthreads();
        }
    }
    float* dst = g_Cp[g >> 6];
#pragma unroll
    for (int p = 0; p < 2; p++) {
#pragma unroll
        for (int n = 0; n < 8; n++) {
            float2 v = unpk2(acc[p * 8 + n]);
            int m = bm0 + 2 * tm + 32 * p;
            int nc = bn0 + 8 * tn + n;
            dst[m * 512 + nc] = v.x;
            dst[(m + 1) * 512 + nc] = v.y;
        }
    }
}

// ----------------------------------------------------------------------------
// stage2: blocks 0..519 = u (4 rows/block); blocks 520..647 = reduce_C.
// ----------------------------------------------------------------------------
__global__ __launch_bounds__(128) void stage2_kernel(const float* __restrict__ nve) {
    const int tid = threadIdx.x;
    const int bx = blockIdx.x;

    if (bx < 520) {
        __shared__ float sv1[512], sv2[512];
        for (int i = tid; i < 512; i += 128) {
            sv1[i] = g_v1[i];
            sv2[i] = g_v2[i];
        }
        __syncthreads();
        const int w = tid >> 5, lane = tid & 31;
        const int m = bx * 4 + w;
        const float* row = nve + (size_t)m * 512;
        float p1 = 0.f, p2 = 0.f;
#pragma unroll
        for (int r = 0; r < 16; r++) {
            float x = row[r * 32 + lane];
            p1 += x * sv1[r * 32 + lane];
            p2 += x * sv2[r * 32 + lane];
        }
        for (int o = 16; o; o >>= 1) {
            p1 += __shfl_xor_sync(0xffffffffu, p1, o);
            p2 += __shfl_xor_sync(0xffffffffu, p2, o);
        }
        if (lane == 0) { g_u1[m] = p1; g_u2[m] = p2; }
        return;
    }

    const int base = (bx - 520) * 128 + tid;
    const float4* p0 = reinterpret_cast<const float4*>(g_Cp[0]);
    const float4* p1 = reinterpret_cast<const float4*>(g_Cp[1]);
    const float4* p2 = reinterpret_cast<const float4*>(g_Cp[2]);
    const float4* p3 = reinterpret_cast<const float4*>(g_Cp[3]);
    float4* dst = reinterpret_cast<float4*>(g_C);
#pragma unroll
    for (int q = 0; q < 4; q++) {
        int i = base + q * 16384;
        float4 a = p0[i], b = p1[i], c = p2[i], d = p3[i];
        float4 r;
        r.x = ((a.x + b.x) + c.x) + d.x;
        r.y = ((a.y + b.y) + c.y) + d.y;
        r.z = ((a.z + b.z) + c.z) + d.z;
        r.w = ((a.w + b.w) + c.w) + d.w;
        dst[i] = r;
    }
}

// ----------------------------------------------------------------------------
// gemm_T: T[m,n] = sum_k nve[m,k] * C[k,n]  (NN, 2080x512x512)
// BM=128, BN=64, BK=32, 128 thr, grid (17,8)=136. Thread tile 8Mx8N.
// DYNAMIC smem 49,664 B. (best measured form)
// ----------------------------------------------------------------------------
__global__ __launch_bounds__(128) void gemm_T_kernel(const float* __restrict__ nve) {
    extern __shared__ __align__(16) float dsm[];
    float* Asf = dsm;                          // [2][32][130]
    float* Bsf = dsm + 2 * 32 * TT_APAD;       // [2][32][64]
#define AS_T(buf, k, m) Asf[((buf) * 32 + (k)) * TT_APAD + (m)]
#define BS_T(buf, k, n) Bsf[((buf) * 32 + (k)) * 64 + (n)]

    const int tid = threadIdx.x;
    const int tm = tid & 15;
    const int tn = tid >> 4;
    const int m0 = blockIdx.x * 128;
    const int n0 = blockIdx.y * 64;

    unsigned long long acc[32];
#pragma unroll
    for (int i = 0; i < 32; i++) acc[i] = 0ull;

    const float4 z4 = make_float4(0.f, 0.f, 0.f, 0.f);
    float4 ra[8], rb[4];
#pragma unroll
    for (int it = 0; it < 8; it++) {
        int idx = tid + it * 128;
        int m = m0 + (idx >> 3), k4 = (idx & 7) * 4;
        ra[it] = (m < MROWS) ? *reinterpret_cast<const float4*>(&nve[m * 512 + k4]) : z4;
    }
#pragma unroll
    for (int it = 0; it < 4; it++) {
        int idx = tid + it * 128;
        int r = idx >> 4, c4 = (idx & 15) * 4;
        rb[it] = *reinterpret_cast<const float4*>(&g_C[r * 512 + n0 + c4]);
    }
#pragma unroll
    for (int it = 0; it < 8; it++) {
        int idx = tid + it * 128;
        int ml = idx >> 3, k4 = (idx & 7) * 4;
        AS_T(0, k4 + 0, ml) = ra[it].x;
        AS_T(0, k4 + 1, ml) = ra[it].y;
        AS_T(0, k4 + 2, ml) = ra[it].z;
        AS_T(0, k4 + 3, ml) = ra[it].w;
    }
#pragma unroll
    for (int it = 0; it < 4; it++) {
        int idx = tid + it * 128;
        int r = idx >> 4, c4 = (idx & 15) * 4;
        *reinterpret_cast<float4*>(&BS_T(0, r, c4)) = rb[it];
    }
    __syncthreads();

    for (int kt = 0; kt < 16; kt++) {
        const int cur = kt & 1, nxt = cur ^ 1;
        if (kt < 15) {
            int k0 = (kt + 1) * 32;
#pragma unroll
            for (int it = 0; it < 8; it++) {
                int idx = tid + it * 128;
                int m = m0 + (idx >> 3), k4 = (idx & 7) * 4;
                ra[it] = (m < MROWS)
                             ? *reinterpret_cast<const float4*>(&nve[m * 512 + k0 + k4])
                             : z4;
            }
#pragma unroll
            for (int it = 0; it < 4; it++) {
                int idx = tid + it * 128;
                int r = idx >> 4, c4 = (idx & 15) * 4;
                rb[it] = *reinterpret_cast<const float4*>(&g_C[(k0 + r) * 512 + n0 + c4]);
            }
        }
#pragma unroll
        for (int k = 0; k < 32; k++) {
            unsigned long long a[4];
#pragma unroll
            for (int p = 0; p < 4; p++)
                a[p] = *reinterpret_cast<const unsigned long long*>(&AS_T(cur, k, 2 * tm + 32 * p));
            float4 b0 = *reinterpret_cast<const float4*>(&BS_T(cur, k, 8 * tn));
            float4 b1 = *reinterpret_cast<const float4*>(&BS_T(cur, k, 8 * tn + 4));
            unsigned long long bb[8] = {bcast2(b0.x), bcast2(b0.y), bcast2(b0.z), bcast2(b0.w),
                                        bcast2(b1.x), bcast2(b1.y), bcast2(b1.z), bcast2(b1.w)};
#pragma unroll
            for (int p = 0; p < 4; p++) {
#pragma unroll
                for (int n = 0; n < 8; n++) fma2(acc[p * 8 + n], a[p], bb[n]);
            }
        }
        if (kt < 15) {
#pragma unroll
            for (int it = 0; it < 8; it++) {
                int idx = tid + it * 128;
                int ml = idx >> 3, k4 = (idx & 7) * 4;
                AS_T(nxt, k4 + 0, ml) = ra[it].x;
                AS_T(nxt, k4 + 1, ml) = ra[it].y;
                AS_T(nxt, k4 + 2, ml) = ra[it].z;
                AS_T(nxt, k4 + 3, ml) = ra[it].w;
            }
#pragma unroll
            for (int it = 0; it < 4; it++) {
                int idx = tid + it * 128;
                int r = idx >> 4, c4 = (idx & 15) * 4;
                *reinterpret_cast<float4*>(&BS_T(nxt, r, c4)) = rb[it];
            }
            __syncthreads();
        }
    }
#pragma unroll
    for (int p = 0; p < 4; p++) {
#pragma unroll
        for (int n = 0; n < 8; n++) {
            float2 v = unpk2(acc[p * 8 + n]);
            int m = m0 + 2 * tm + 32 * p;
            int nc = n0 + 8 * tn + n;
            if (m < MROWS) g_T[m * 512 + nc] = v.x;
            if (m + 1 < MROWS) g_T[(m + 1) * 512 + nc] = v.y;
        }
    }
#undef AS_T
#undef BS_T
}

// ----------------------------------------------------------------------------
// score_kernel: S[i,j] = T[b,i,:].nve[b,j,:] for 16 i-rows, j in [0,65).
// R17: 128 thr, BK=32, thread tile 2Mx4N + col64 (tn==0). Grid (4, BB).
// As[2][32][18] transposed; Bs[2][32][68] transposed. Same k-order/pairing
// per element as before (bit-identical scores).
// ----------------------------------------------------------------------------
__global__ __launch_bounds__(128) void score_kernel(const float* __restrict__ nve) {
    __shared__ __align__(16) float As[2][32][18];
    __shared__ __align__(16) float Bs[2][32][68];
    __shared__ float sS[16][68];
    __shared__ float su1[16];
    __shared__ float su2[65];

    const int b = blockIdx.y;
    const int i0 = 1 + 16 * blockIdx.x;
    const int tid = threadIdx.x;
    const int tm = tid & 7;        // rows 2tm, 2tm+1
    const int tn = tid >> 3;       // cols 4tn..4tn+3 (0..15); col 64 if tn==0

    if (tid < 16) su1[tid] = g_u1[b * 65 + i0 + tid];
    else if (tid < 16 + 65) su2[tid - 16] = g_u2[b * 65 + (tid - 16)];

    const float* Tb = g_T + ((size_t)b * 65 + i0) * 512;
    const float* Nb = nve + (size_t)b * 65 * 512;

    unsigned long long acc[4] = {0ull, 0ull, 0ull, 0ull};
    unsigned long long acc64 = 0ull;

    // A tile: 16 rows x 32 k = 128 float4 (1/thread): arow=tid>>3, ak4=(tid&7)*4
    // B tile: 65 rows x 32 k = 520 float4: idx = tid + it*128, idx < 520
    const int arow = tid >> 3, ak4 = (tid & 7) * 4;
    float4 ra4, rb4[5];
    {
        ra4 = *reinterpret_cast<const float4*>(&Tb[arow * 512 + ak4]);
#pragma unroll
        for (int it = 0; it < 5; it++) {
            int idx = tid + it * 128;
            if (idx < 520) {
                int j = idx >> 3, k4 = (idx & 7) * 4;
                rb4[it] = *reinterpret_cast<const float4*>(&Nb[j * 512 + k4]);
            }
        }
        As[0][ak4 + 0][arow] = ra4.x;
        As[0][ak4 + 1][arow] = ra4.y;
        As[0][ak4 + 2][arow] = ra4.z;
        As[0][ak4 + 3][arow] = ra4.w;
#pragma unroll
        for (int it = 0; it < 5; it++) {
            int idx = tid + it * 128;
            if (idx < 520) {
                int j = idx >> 3, k4 = (idx & 7) * 4;
                Bs[0][k4 + 0][j] = rb4[it].x;
                Bs[0][k4 + 1][j] = rb4[it].y;
                Bs[0][k4 + 2][j] = rb4[it].z;
                Bs[0][k4 + 3][j] = rb4[it].w;
            }
        }
    }
    __syncthreads();

    for (int kt = 0; kt < 16; kt++) {
        const int cur = kt & 1, nxt = cur ^ 1;
        if (kt < 15) {
            int k0 = (kt + 1) * 32;
            ra4 = *reinterpret_cast<const float4*>(&Tb[arow * 512 + k0 + ak4]);
#pragma unroll
            for (int it = 0; it < 5; it++) {
                int idx = tid + it * 128;
                if (idx < 520) {
                    int j = idx >> 3, k4 = (idx & 7) * 4;
                    rb4[it] = *reinterpret_cast<const float4*>(&Nb[j * 512 + k0 + k4]);
                }
            }
        }
#pragma unroll
        for (int k = 0; k < 32; k++) {
            unsigned long long a = *reinterpret_cast<const unsigned long long*>(&As[cur][k][2 * tm]);
            float4 bv = *reinterpret_cast<const float4*>(&Bs[cur][k][4 * tn]);
            fma2(acc[0], a, bcast2(bv.x));
            fma2(acc[1], a, bcast2(bv.y));
            fma2(acc[2], a, bcast2(bv.z));
            fma2(acc[3], a, bcast2(bv.w));
            if (tn == 0) fma2(acc64, a, bcast2(Bs[cur][k][64]));
        }
        if (kt < 15) {
            As[nxt][ak4 + 0][arow] = ra4.x;
            As[nxt][ak4 + 1][arow] = ra4.y;
            As[nxt][ak4 + 2][arow] = ra4.z;
            As[nxt][ak4 + 3][arow] = ra4.w;
#pragma unroll
            for (int it = 0; it < 5; it++) {
                int idx = tid + it * 128;
                if (idx < 520) {
                    int j = idx >> 3, k4 = (idx & 7) * 4;
                    Bs[nxt][k4 + 0][j] = rb4[it].x;
                    Bs[nxt][k4 + 1][j] = rb4[it].y;
                    Bs[nxt][k4 + 2][j] = rb4[it].z;
                    Bs[nxt][k4 + 3][j] = rb4[it].w;
                }
            }
            __syncthreads();
        }
    }

#pragma unroll
    for (int q = 0; q < 4; q++) {
        float2 v = unpk2(acc[q]);
        sS[2 * tm][4 * tn + q] = v.x;
        sS[2 * tm + 1][4 * tn + q] = v.y;
    }
    if (tn == 0) {
        float2 v = unpk2(acc64);
        sS[2 * tm][64] = v.x;
        sS[2 * tm + 1][64] = v.y;
    }
    __syncthreads();

    // softmax + threshold: 4 warps, 4 rows per warp
    const int w = tid >> 5, lane = tid & 31;
    const unsigned FULL = 0xffffffffu;
    const float INV_SQRTD = 0.044194173824159216f;
    const float s0 = g_s0;
#pragma unroll
    for (int rr = 0; rr < 4; rr++) {
        int r = w * 4 + rr;
        int i = i0 + r;
        float base = su1[r] + s0;
        int j1 = 32 + lane;
        float L0 = (lane == i) ? 0.f : (sS[r][lane] + base + su2[lane]) * INV_SQRTD;
        float L1 = (j1 == i) ? 0.f : (sS[r][j1] + base + su2[j1]) * INV_SQRTD;
        float L2 = (lane == 0)
                       ? ((i == 64) ? 0.f : (sS[r][64] + base + su2[64]) * INV_SQRTD)
                       : -1e30f;
        float mx = fmaxf(L0, fmaxf(L1, L2));
        for (int o = 16; o; o >>= 1) mx = fmaxf(mx, __shfl_xor_sync(FULL, mx, o));
        float e0 = expf(L0 - mx);
        float e1 = expf(L1 - mx);
        float e2 = (lane == 0) ? expf(L2 - mx) : 0.f;
        float sm = e0 + e1 + e2;
        for (int o = 16; o; o >>= 1) sm += __shfl_xor_sync(FULL, sm, o);
        float inv = 1.0f / sm;
        unsigned bal0 = __ballot_sync(FULL, (lane >= 1) && (e0 * inv > 0.05f));
        unsigned bal1 = __ballot_sync(FULL, e1 * inv > 0.05f);
        unsigned bal2 = __ballot_sync(FULL, (lane == 0) && (e2 * inv > 0.05f));
        if (lane == 0) {
            unsigned long long m = ((unsigned long long)(bal0 >> 1)) |
                                   ((unsigned long long)bal1 << 31) |
                                   ((unsigned long long)(bal2 & 1u) << 63);
            m |= 1ull << (i - 1);
            g_rawmask[b * 64 + (i - 1)] = m;
        }
    }
}

// ----------------------------------------------------------------------------
// cluster: greedy sequential clustering per batch + leader/member outputs
// ----------------------------------------------------------------------------
__global__ __launch_bounds__(256) void cluster_kernel(float* __restrict__ out) {
    __shared__ unsigned long long sm[64];
    __shared__ unsigned long long sf[64];
    __shared__ unsigned long long sl;
    const int b = blockIdx.x;
    const int tid = threadIdx.x;
    if (tid < 64) sm[tid] = g_rawmask[b * 64 + tid];
    __syncthreads();
    if (tid == 0) {
        unsigned long long used = 0ull, lead = 0ull;
        for (int i = 0; i < 64; i++) {
            unsigned long long m = sm[i];
            if (!((used >> i) & 1ull)) {
                lead |= 1ull << i;
                used |= m;
                sf[i] = m;
            } else {
                sf[i] = 0ull;
            }
        }
        sl = lead;
    }
    __syncthreads();
    unsigned long long lead = sl;
    if (tid < 64) {
        out[LEADER_OFF + (size_t)b * 64 + tid] = ((lead >> tid) & 1ull) ? 1.0f : 0.0f;
        g_mmask[b * 64 + tid] = sf[tid];
    }
    for (int idx = tid; idx < 4096; idx += 256) {
        out[MEMBER_OFF + (size_t)b * 4096 + idx] =
            ((sf[idx >> 6] >> (idx & 63)) & 1ull) ? 1.0f : 0.0f;
    }
}

// ----------------------------------------------------------------------------
// expansion: write-bandwidth bound (~273 MB), streaming stores.
// ----------------------------------------------------------------------------
__global__ __launch_bounds__(256) void expand_kernel(const float* __restrict__ nve,
                                                     const float* __restrict__ cls,
                                                     float* __restrict__ out) {
    const int bi = blockIdx.x;
    const int b = bi >> 6;
    const unsigned long long mask = g_mmask[bi];
    const bool lead = (mask != 0ull);

    const float4* nve4 = reinterpret_cast<const float4*>(nve);
    const float4* cls4 = reinterpret_cast<const float4*>(cls);
    float4* out4 = reinterpret_cast<float4*>(out) + (size_t)bi * 65 * 128;

    const int quad = threadIdx.x & 127;
    const int sub = threadIdx.x >> 7;
    const float4 zero4 = make_float4(0.f, 0.f, 0.f, 0.f);

    for (int r = sub; r < 65; r += 2) {
        float4 v;
        if (r == 0) {
            v = lead ? cls4[quad] : zero4;
        } else {
            v = ((mask >> (r - 1)) & 1ull) ? nve4[((size_t)b * 65 + r) * 128 + quad]
                                           : zero4;
        }
        __stcs(&out4[(size_t)r * 128 + quad], v);
    }
}

// ----------------------------------------------------------------------------
extern "C" void kernel_launch(void* const* d_in, const int* in_sizes, int n_in,
                              void* d_out, int out_size) {
    // inputs: desc_embeddings, name_value_embeddings, Wq, bq, Wk, bk, cls
    const float* nve = (const float*)d_in[1];
    const float* Wq  = (const float*)d_in[2];
    const float* bq  = (const float*)d_in[3];
    const float* Wk  = (const float*)d_in[4];
    const float* bk  = (const float*)d_in[5];
    const float* cls = (const float*)d_in[6];
    float* out = (float*)d_out;

    cudaFuncSetAttribute(gemm_T_kernel, cudaFuncAttributeMaxDynamicSharedMemorySize,
                         GT_SMEM);

    stage1_kernel<<<288, 128>>>(Wq, bq, Wk, bk);
    stage2_kernel<<<648, 128>>>(nve);
    gemm_T_kernel<<<dim3(17, 8), 128, GT_SMEM>>>(nve);
    score_kernel<<<dim3(4, BB), 128>>>(nve);
    cluster_kernel<<<BB, 256>>>(out);
    expand_kernel<<<BB * SS, 256>>>(nve, cls, out);
}